// round 15
// baseline (speedup 1.0000x reference)
#include <cuda_runtime.h>
#include <cuda_fp16.h>
#include <cstdint>

#define B_  2
#define L_  512
#define T_  1024
#define E_  2560
#define H_  128
#define F_  (2*E_)   // 5120
#define TSH 48       // halves per (l,h) in ts: q[20] pad[4] k[20] pad[4]

// Scratch (no cudaMalloc allowed)
__device__ __half g_xh [B_*L_*T_];      // x fp16        2 MB
__device__ __half g_wuh[E_*T_];         // W_up fp16     5 MB
__device__ __half g_wph[F_*E_];         // W_proj fp16   26 MB
__device__ __half g_xeh[B_*L_*E_];      // xe fp16       5 MB
__device__ __half g_ts [B_*L_*H_*TSH]; // split q|k fp16 12.6 MB

// ---------------------------------------------------------------------------
// helpers
// ---------------------------------------------------------------------------
__device__ __forceinline__ uint32_t smem_u32(const void* p) {
    uint32_t a;
    asm("{ .reg .u64 t; cvta.to.shared.u64 t, %1; cvt.u32.u64 %0, t; }"
        : "=r"(a) : "l"(p));
    return a;
}

__device__ __forceinline__ void cp_async16(uint32_t smem, const void* g) {
    asm volatile("cp.async.cg.shared.global [%0], [%1], 16;" :: "r"(smem), "l"(g));
}

__device__ __forceinline__ void ldsm_x4(uint32_t (&r)[4], uint32_t addr) {
    asm volatile("ldmatrix.sync.aligned.m8n8.x4.shared.b16 {%0,%1,%2,%3}, [%4];"
                 : "=r"(r[0]), "=r"(r[1]), "=r"(r[2]), "=r"(r[3]) : "r"(addr));
}

__device__ __forceinline__ void mma_f16(float (&d)[4], const uint32_t (&a)[4],
                                        const uint32_t b0, const uint32_t b1) {
    asm volatile(
        "mma.sync.aligned.m16n8k16.row.col.f32.f16.f16.f32 "
        "{%0,%1,%2,%3}, {%4,%5,%6,%7}, {%8,%9}, {%0,%1,%2,%3};"
        : "+f"(d[0]), "+f"(d[1]), "+f"(d[2]), "+f"(d[3])
        : "r"(a[0]), "r"(a[1]), "r"(a[2]), "r"(a[3]), "r"(b0), "r"(b1));
}

// ---------------------------------------------------------------------------
// merged f32 -> f16 conversion for x, W_up, W_proj (single launch)
// ---------------------------------------------------------------------------
#define N4_X   (B_*L_*T_/4)            // 262144
#define N4_WU  (E_*T_/4)               // 655360
#define N4_WP  (F_*E_/4)               // 3276800
#define N4_ALL (N4_X + N4_WU + N4_WP)  // 4194304

__global__ void f2h_all_kernel(const float4* __restrict__ x,
                               const float4* __restrict__ wu,
                               const float4* __restrict__ wp,
                               uint2* __restrict__ xh,
                               uint2* __restrict__ wuh,
                               uint2* __restrict__ wph)
{
    for (int i = blockIdx.x * blockDim.x + threadIdx.x; i < N4_ALL;
         i += gridDim.x * blockDim.x) {
        const float4* src;
        uint2* dst;
        int j;
        if (i < N4_X)                { src = x;  dst = xh;  j = i; }
        else if (i < N4_X + N4_WU)   { src = wu; dst = wuh; j = i - N4_X; }
        else                         { src = wp; dst = wph; j = i - N4_X - N4_WU; }
        float4 v = src[j];
        __half2 lo = __floats2half2_rn(v.x, v.y);
        __half2 hi = __floats2half2_rn(v.z, v.w);
        uint2 o;
        o.x = *(const uint32_t*)&lo;
        o.y = *(const uint32_t*)&hi;
        dst[j] = o;
    }
}

// ---------------------------------------------------------------------------
// fp16 GEMM (R8/R12 verbatim): C[M,N] = A[M,K] * W[N,K]^T, 64x128x32 tiles,
// 8 warps (2m x 4n), warp tile 32x32, 4-stage cp.async, 80B rows.
// MODE 0: plain __half row-major out.  MODE 2: split-ts out.
// ---------------------------------------------------------------------------
#define BMT 64
#define BN 128
#define BK 32
#define STAGES 4
#define ROWB 80
#define A_BYTES (BMT*ROWB)
#define STGB ((BMT+BN)*ROWB)
#define GSMEM_BYTES (STGB*STAGES)    // 61440

template <int MODE>
__global__ void __launch_bounds__(256, 2) gemm_f16(
    const __half* __restrict__ A, const __half* __restrict__ W,
    __half* __restrict__ C, int M, int N, int K)
{
    extern __shared__ __align__(16) char gsm[];
    const uint32_t sBase = smem_u32(gsm);

    const int tid  = threadIdx.x;
    const int warp = tid >> 5;
    const int lane = tid & 31;
    const int wm = (warp >> 2) * 32;
    const int wn = (warp & 3) * 32;
    const int m0 = blockIdx.x * BMT;
    const int n0 = blockIdx.y * BN;

    float acc[2][4][4];
    #pragma unroll
    for (int i = 0; i < 2; ++i)
        #pragma unroll
        for (int j = 0; j < 4; ++j)
            #pragma unroll
            for (int v = 0; v < 4; ++v) acc[i][j][v] = 0.0f;

    const int KT = K / BK;
    const int lrow = tid >> 2;
    const int lch  = (tid & 3) * 8;

    #define LOAD_STAGE(st, kt)                                                  \
    {                                                                           \
        const int kb = (kt) * BK;                                               \
        const uint32_t as = sBase + (st) * STGB;                                \
        const uint32_t ws = as + A_BYTES;                                       \
        cp_async16(as + lrow * ROWB + lch * 2,                                  \
                   &A[(size_t)(m0 + lrow) * K + kb + lch]);                     \
        _Pragma("unroll")                                                       \
        for (int i = 0; i < 2; ++i) {                                           \
            int row = lrow + i * 64;                                            \
            cp_async16(ws + row * ROWB + lch * 2,                               \
                       &W[(size_t)(n0 + row) * K + kb + lch]);                  \
        }                                                                       \
        asm volatile("cp.async.commit_group;");                                 \
    }

    LOAD_STAGE(0, 0);
    LOAD_STAGE(1, 1);
    LOAD_STAGE(2, 2);

    const int sel  = lane >> 3;
    const int lr8  = lane & 7;
    const int selR = (sel & 1) * 8;
    const int selK = (sel >> 1) * 16;

    for (int kt = 0; kt < KT; ++kt) {
        asm volatile("cp.async.wait_group 2;");
        __syncthreads();

        const int st = kt & 3;
        const uint32_t as = sBase + st * STGB;
        const uint32_t ws = as + A_BYTES;

        #pragma unroll
        for (int s = 0; s < 2; ++s) {
            const int kbyte = s * 32 + selK;
            uint32_t af[2][4];
            #pragma unroll
            for (int i = 0; i < 2; ++i) {
                int m = wm + i * 16 + selR + lr8;
                ldsm_x4(af[i], as + m * ROWB + kbyte);
            }
            uint32_t bf[4][2];
            #pragma unroll
            for (int j2 = 0; j2 < 2; ++j2) {
                uint32_t r[4];
                int n = wn + j2 * 16 + selR + lr8;
                ldsm_x4(r, ws + n * ROWB + kbyte);
                bf[j2*2][0]   = r[0]; bf[j2*2][1]   = r[2];
                bf[j2*2+1][0] = r[1]; bf[j2*2+1][1] = r[3];
            }
            #pragma unroll
            for (int i = 0; i < 2; ++i)
                #pragma unroll
                for (int j = 0; j < 4; ++j)
                    mma_f16(acc[i][j], af[i], bf[j][0], bf[j][1]);
        }
        __syncthreads();

        if (kt + 3 < KT) {
            LOAD_STAGE((kt + 3) & 3, kt + 3);
        } else {
            asm volatile("cp.async.commit_group;");
        }
    }

    const int er = lane >> 2;
    const int ec = (lane & 3) * 2;
    #pragma unroll
    for (int i = 0; i < 2; ++i) {
        #pragma unroll
        for (int j = 0; j < 4; ++j) {
            int m = m0 + wm + i * 16 + er;
            int n = n0 + wn + j * 8 + ec;
            if (MODE == 0) {
                __half2 h0 = __floats2half2_rn(acc[i][j][0], acc[i][j][1]);
                __half2 h1 = __floats2half2_rn(acc[i][j][2], acc[i][j][3]);
                *(__half2*)(C + (size_t)m * N + n)       = h0;
                *(__half2*)(C + (size_t)(m + 8) * N + n) = h1;
            } else {
                int h  = n / 40;
                int cc = n % 40;
                bool isq = cc < 20;
                int pos = isq ? cc : cc + 4;
                float s = isq ? 0.22360679774997896f : 1.0f;
                __half2 h0 = __floats2half2_rn(acc[i][j][0] * s, acc[i][j][1] * s);
                __half2 h1 = __floats2half2_rn(acc[i][j][2] * s, acc[i][j][3] * s);
                *(__half2*)(C + ((size_t)m * H_ + h) * TSH + pos)       = h0;
                *(__half2*)(C + ((size_t)(m + 8) * H_ + h) * TSH + pos) = h1;
            }
        }
    }
    #undef LOAD_STAGE
}

// ---------------------------------------------------------------------------
// Epilogue v10: v9 structure, BRANCHLESS mask -> out = maskf*(dot + bias).
// Uniform control flow lets ptxas front-batch all bias LDG.64 + k LDS per
// iteration (MLP ~16 vs ~2), hiding DRAM latency. Masked outputs exact 0.
// block = (head-chunk 8h, q-tile 32, b); 16 k-iterations of 32 rows.
// Thread: hp = tid&3 (2 heads), qg = (tid>>2)&15 (2 q rows), kg = tid>>6.
// q: 2 rows x 2 heads x 10 half2 in regs; k smem 8 planes x 776 halves.
// ---------------------------------------------------------------------------
#define PLANEH 776
#define EPKH (8*PLANEH)   // 12416 B

__global__ void __launch_bounds__(256, 3) attn_epilogue_kernel(
    const __half* __restrict__ ts, const int* __restrict__ mask,
    const float* __restrict__ bias, float* __restrict__ out)
{
    __shared__ __align__(16) __half ks[EPKH];

    const int b  = blockIdx.z;
    const int q0 = blockIdx.y * 32;
    const int h0 = blockIdx.x * 8;
    const int tid = threadIdx.x;
    const int hp = tid & 3;          // head pair: local heads 2hp, 2hp+1
    const int qg = (tid >> 2) & 15;  // 2 q rows each
    const int kg = tid >> 6;         // 8 k rows per iter
    const int frow = tid >> 3;       // fill: 0..31
    const int fh   = tid & 7;        // fill: 0..7

    // ---- load q: 2 rows x 2 heads (h0+2hp, h0+2hp+1), once ----
    __half2 qh[2][2][10];
    {
        const size_t qrow_base = (size_t)(b * L_ + q0 + qg * 2) * H_;
        #pragma unroll
        for (int qq = 0; qq < 2; ++qq) {
            #pragma unroll
            for (int hh = 0; hh < 2; ++hh) {
                const __half* qsrc =
                    ts + (qrow_base + (size_t)qq * H_ + h0 + 2 * hp + hh) * TSH;
                uint4 v0 = *(const uint4*)qsrc;
                uint4 v1 = *(const uint4*)(qsrc + 8);
                uint2 v2 = *(const uint2*)(qsrc + 16);
                qh[qq][hh][0] = *(const __half2*)&v0.x;
                qh[qq][hh][1] = *(const __half2*)&v0.y;
                qh[qq][hh][2] = *(const __half2*)&v0.z;
                qh[qq][hh][3] = *(const __half2*)&v0.w;
                qh[qq][hh][4] = *(const __half2*)&v1.x;
                qh[qq][hh][5] = *(const __half2*)&v1.y;
                qh[qq][hh][6] = *(const __half2*)&v1.z;
                qh[qq][hh][7] = *(const __half2*)&v1.w;
                qh[qq][hh][8] = *(const __half2*)&v2.x;
                qh[qq][hh][9] = *(const __half2*)&v2.y;
            }
        }
    }

    for (int kt = 0; kt < 16; ++kt) {
        const int k0 = kt * 32;
        __syncthreads();   // previous iteration's consumers done with ks

        // fill k plane: one (row, head) segment per thread, raw 24-half copy
        {
            const __half* ksrc = ts + ((size_t)(b * L_ + k0 + frow) * H_ + h0 + fh) * TSH + 24;
            __half* kdst = ks + fh * PLANEH + frow * 24;
            *(uint4*)(kdst)      = *(const uint4*)(ksrc);
            *(uint4*)(kdst + 8)  = *(const uint4*)(ksrc + 8);
            *(uint4*)(kdst + 16) = *(const uint4*)(ksrc + 16);
        }
        __syncthreads();   // k plane visible

        // mask as float multiplier (0.0 / 1.0) -> branchless
        float mkf[8];
        #pragma unroll
        for (int kk = 0; kk < 8; ++kk)
            mkf[kk] = (float)mask[b * L_ + k0 + kg * 8 + kk];

        const size_t obase = ((size_t)(b * L_ + q0 + qg * 2) * L_ + k0 + kg * 8) * H_
                           + h0 + 2 * hp;

        #pragma unroll
        for (int kk = 0; kk < 8; ++kk) {
            size_t okk = obase + (size_t)kk * H_;
            float d[2][2];     // [qq][hh]
            #pragma unroll
            for (int hh = 0; hh < 2; ++hh) {
                __half2 kvh[10];
                const __half* kp = ks + (2 * hp + hh) * PLANEH
                                 + (kg * 8 + kk) * 24;
                uint4 a0 = *(const uint4*)kp;
                uint4 a1 = *(const uint4*)(kp + 8);
                uint2 a2 = *(const uint2*)(kp + 16);
                kvh[0] = *(const __half2*)&a0.x;
                kvh[1] = *(const __half2*)&a0.y;
                kvh[2] = *(const __half2*)&a0.z;
                kvh[3] = *(const __half2*)&a0.w;
                kvh[4] = *(const __half2*)&a1.x;
                kvh[5] = *(const __half2*)&a1.y;
                kvh[6] = *(const __half2*)&a1.z;
                kvh[7] = *(const __half2*)&a1.w;
                kvh[8] = *(const __half2*)&a2.x;
                kvh[9] = *(const __half2*)&a2.y;
                #pragma unroll
                for (int qq = 0; qq < 2; ++qq) {
                    __half2 acc0 = __hmul2(qh[qq][hh][0], kvh[0]);
                    __half2 acc1 = __hmul2(qh[qq][hh][1], kvh[1]);
                    #pragma unroll
                    for (int c = 1; c < 5; ++c) {
                        acc0 = __hfma2(qh[qq][hh][2*c],   kvh[2*c],   acc0);
                        acc1 = __hfma2(qh[qq][hh][2*c+1], kvh[2*c+1], acc1);
                    }
                    float2 f0 = __half22float2(acc0);
                    float2 f1 = __half22float2(acc1);
                    d[qq][hh] = (f0.x + f0.y) + (f1.x + f1.y);
                }
            }
            #pragma unroll
            for (int qq = 0; qq < 2; ++qq) {
                size_t oidx = okk + (size_t)qq * (L_ * H_);
                float2 bv = *(const float2*)&bias[oidx];
                float2 ov;
                ov.x = mkf[kk] * (d[qq][0] + bv.x);
                ov.y = mkf[kk] * (d[qq][1] + bv.y);
                *(float2*)&out[oidx] = ov;
            }
        }
    }
}

// ---------------------------------------------------------------------------
// launch: f2h_all(1), GEMM1(2), GEMM2(3), epilogue(4 -> profiled)
// ---------------------------------------------------------------------------
extern "C" void kernel_launch(void* const* d_in, const int* in_sizes, int n_in,
                              void* d_out, int out_size)
{
    const float* x      = (const float*)d_in[0];   // (B,L,T)
    const int*   mask   = (const int*)  d_in[1];   // (B,L) int32
    const float* bias   = (const float*)d_in[2];   // (B,L,L,H)
    const float* W_up   = (const float*)d_in[3];   // (E,T)
    const float* W_proj = (const float*)d_in[4];   // (2E,E)
    float* out = (float*)d_out;

    __half *xh, *wuh, *wph, *xeh, *ts;
    cudaGetSymbolAddress((void**)&xh,  g_xh);
    cudaGetSymbolAddress((void**)&wuh, g_wuh);
    cudaGetSymbolAddress((void**)&wph, g_wph);
    cudaGetSymbolAddress((void**)&xeh, g_xeh);
    cudaGetSymbolAddress((void**)&ts,  g_ts);

    cudaFuncSetAttribute((const void*)gemm_f16<0>,
                         cudaFuncAttributeMaxDynamicSharedMemorySize, GSMEM_BYTES);
    cudaFuncSetAttribute((const void*)gemm_f16<2>,
                         cudaFuncAttributeMaxDynamicSharedMemorySize, GSMEM_BYTES);

    // merged f32 -> f16 conversion (one launch)
    f2h_all_kernel<<<2368, 256>>>((const float4*)x, (const float4*)W_up,
                                  (const float4*)W_proj,
                                  (uint2*)xh, (uint2*)wuh, (uint2*)wph);

    // GEMM1: xe_h(1024,2560) = x_h @ W_up_h^T   (320 CTAs)
    {
        dim3 grid(B_*L_ / BMT, E_ / BN);
        gemm_f16<0><<<grid, 256, GSMEM_BYTES>>>(xh, wuh, xeh, B_*L_, E_, T_);
    }
    // GEMM2: ts split layout = xe_h @ W_proj_h^T  (640 CTAs)
    {
        dim3 grid(B_*L_ / BMT, F_ / BN);
        gemm_f16<2><<<grid, 256, GSMEM_BYTES>>>(xeh, wph, ts, B_*L_, F_, E_);
    }
    // fused q.k^T + bias + mask epilogue
    {
        dim3 grid(H_ / 8, L_ / 32, B_);
        attn_epilogue_kernel<<<grid, 256>>>(ts, mask, bias, out);
    }
}

// round 16
// speedup vs baseline: 1.2143x; 1.2143x over previous
#include <cuda_runtime.h>
#include <cuda_fp16.h>
#include <cstdint>

#define B_  2
#define L_  512
#define T_  1024
#define E_  2560
#define H_  128
#define F_  (2*E_)   // 5120
#define TSH 48       // halves per (l,h) in ts: q[20] pad[4] k[20] pad[4]

// Scratch (no cudaMalloc allowed)
__device__ __half g_xh [B_*L_*T_];      // x fp16        2 MB
__device__ __half g_wuh[E_*T_];         // W_up fp16     5 MB
__device__ __half g_wph[F_*E_];         // W_proj fp16   26 MB
__device__ __half g_xeh[B_*L_*E_];      // xe fp16       5 MB
__device__ __half g_ts [B_*L_*H_*TSH]; // split q|k fp16 12.6 MB

// ---------------------------------------------------------------------------
// helpers
// ---------------------------------------------------------------------------
__device__ __forceinline__ uint32_t smem_u32(const void* p) {
    uint32_t a;
    asm("{ .reg .u64 t; cvta.to.shared.u64 t, %1; cvt.u32.u64 %0, t; }"
        : "=r"(a) : "l"(p));
    return a;
}

__device__ __forceinline__ void cp_async16(uint32_t smem, const void* g) {
    asm volatile("cp.async.cg.shared.global [%0], [%1], 16;" :: "r"(smem), "l"(g));
}

__device__ __forceinline__ void ldsm_x4(uint32_t (&r)[4], uint32_t addr) {
    asm volatile("ldmatrix.sync.aligned.m8n8.x4.shared.b16 {%0,%1,%2,%3}, [%4];"
                 : "=r"(r[0]), "=r"(r[1]), "=r"(r[2]), "=r"(r[3]) : "r"(addr));
}

__device__ __forceinline__ void mma_f16(float (&d)[4], const uint32_t (&a)[4],
                                        const uint32_t b0, const uint32_t b1) {
    asm volatile(
        "mma.sync.aligned.m16n8k16.row.col.f32.f16.f16.f32 "
        "{%0,%1,%2,%3}, {%4,%5,%6,%7}, {%8,%9}, {%0,%1,%2,%3};"
        : "+f"(d[0]), "+f"(d[1]), "+f"(d[2]), "+f"(d[3])
        : "r"(a[0]), "r"(a[1]), "r"(a[2]), "r"(a[3]), "r"(b0), "r"(b1));
}

// ---------------------------------------------------------------------------
// merged f32 -> f16 conversion for x, W_up, W_proj (single launch)
// ---------------------------------------------------------------------------
#define N4_X   (B_*L_*T_/4)            // 262144
#define N4_WU  (E_*T_/4)               // 655360
#define N4_WP  (F_*E_/4)               // 3276800
#define N4_ALL (N4_X + N4_WU + N4_WP)  // 4194304

__global__ void f2h_all_kernel(const float4* __restrict__ x,
                               const float4* __restrict__ wu,
                               const float4* __restrict__ wp,
                               uint2* __restrict__ xh,
                               uint2* __restrict__ wuh,
                               uint2* __restrict__ wph)
{
    for (int i = blockIdx.x * blockDim.x + threadIdx.x; i < N4_ALL;
         i += gridDim.x * blockDim.x) {
        const float4* src;
        uint2* dst;
        int j;
        if (i < N4_X)                { src = x;  dst = xh;  j = i; }
        else if (i < N4_X + N4_WU)   { src = wu; dst = wuh; j = i - N4_X; }
        else                         { src = wp; dst = wph; j = i - N4_X - N4_WU; }
        float4 v = src[j];
        __half2 lo = __floats2half2_rn(v.x, v.y);
        __half2 hi = __floats2half2_rn(v.z, v.w);
        uint2 o;
        o.x = *(const uint32_t*)&lo;
        o.y = *(const uint32_t*)&hi;
        dst[j] = o;
    }
}

// ---------------------------------------------------------------------------
// fp16 GEMM (R8/R12 verbatim): C[M,N] = A[M,K] * W[N,K]^T, 64x128x32 tiles,
// 8 warps (2m x 4n), warp tile 32x32, 4-stage cp.async, 80B rows.
// MODE 0: plain __half row-major out.  MODE 2: split-ts out.
// ---------------------------------------------------------------------------
#define BMT 64
#define BN 128
#define BK 32
#define STAGES 4
#define ROWB 80
#define A_BYTES (BMT*ROWB)
#define STGB ((BMT+BN)*ROWB)
#define GSMEM_BYTES (STGB*STAGES)    // 61440

template <int MODE>
__global__ void __launch_bounds__(256, 2) gemm_f16(
    const __half* __restrict__ A, const __half* __restrict__ W,
    __half* __restrict__ C, int M, int N, int K)
{
    extern __shared__ __align__(16) char gsm[];
    const uint32_t sBase = smem_u32(gsm);

    const int tid  = threadIdx.x;
    const int warp = tid >> 5;
    const int lane = tid & 31;
    const int wm = (warp >> 2) * 32;
    const int wn = (warp & 3) * 32;
    const int m0 = blockIdx.x * BMT;
    const int n0 = blockIdx.y * BN;

    float acc[2][4][4];
    #pragma unroll
    for (int i = 0; i < 2; ++i)
        #pragma unroll
        for (int j = 0; j < 4; ++j)
            #pragma unroll
            for (int v = 0; v < 4; ++v) acc[i][j][v] = 0.0f;

    const int KT = K / BK;
    const int lrow = tid >> 2;
    const int lch  = (tid & 3) * 8;

    #define LOAD_STAGE(st, kt)                                                  \
    {                                                                           \
        const int kb = (kt) * BK;                                               \
        const uint32_t as = sBase + (st) * STGB;                                \
        const uint32_t ws = as + A_BYTES;                                       \
        cp_async16(as + lrow * ROWB + lch * 2,                                  \
                   &A[(size_t)(m0 + lrow) * K + kb + lch]);                     \
        _Pragma("unroll")                                                       \
        for (int i = 0; i < 2; ++i) {                                           \
            int row = lrow + i * 64;                                            \
            cp_async16(ws + row * ROWB + lch * 2,                               \
                       &W[(size_t)(n0 + row) * K + kb + lch]);                  \
        }                                                                       \
        asm volatile("cp.async.commit_group;");                                 \
    }

    LOAD_STAGE(0, 0);
    LOAD_STAGE(1, 1);
    LOAD_STAGE(2, 2);

    const int sel  = lane >> 3;
    const int lr8  = lane & 7;
    const int selR = (sel & 1) * 8;
    const int selK = (sel >> 1) * 16;

    for (int kt = 0; kt < KT; ++kt) {
        asm volatile("cp.async.wait_group 2;");
        __syncthreads();

        const int st = kt & 3;
        const uint32_t as = sBase + st * STGB;
        const uint32_t ws = as + A_BYTES;

        #pragma unroll
        for (int s = 0; s < 2; ++s) {
            const int kbyte = s * 32 + selK;
            uint32_t af[2][4];
            #pragma unroll
            for (int i = 0; i < 2; ++i) {
                int m = wm + i * 16 + selR + lr8;
                ldsm_x4(af[i], as + m * ROWB + kbyte);
            }
            uint32_t bf[4][2];
            #pragma unroll
            for (int j2 = 0; j2 < 2; ++j2) {
                uint32_t r[4];
                int n = wn + j2 * 16 + selR + lr8;
                ldsm_x4(r, ws + n * ROWB + kbyte);
                bf[j2*2][0]   = r[0]; bf[j2*2][1]   = r[2];
                bf[j2*2+1][0] = r[1]; bf[j2*2+1][1] = r[3];
            }
            #pragma unroll
            for (int i = 0; i < 2; ++i)
                #pragma unroll
                for (int j = 0; j < 4; ++j)
                    mma_f16(acc[i][j], af[i], bf[j][0], bf[j][1]);
        }
        __syncthreads();

        if (kt + 3 < KT) {
            LOAD_STAGE((kt + 3) & 3, kt + 3);
        } else {
            asm volatile("cp.async.commit_group;");
        }
    }

    const int er = lane >> 2;
    const int ec = (lane & 3) * 2;
    #pragma unroll
    for (int i = 0; i < 2; ++i) {
        #pragma unroll
        for (int j = 0; j < 4; ++j) {
            int m = m0 + wm + i * 16 + er;
            int n = n0 + wn + j * 8 + ec;
            if (MODE == 0) {
                __half2 h0 = __floats2half2_rn(acc[i][j][0], acc[i][j][1]);
                __half2 h1 = __floats2half2_rn(acc[i][j][2], acc[i][j][3]);
                *(__half2*)(C + (size_t)m * N + n)       = h0;
                *(__half2*)(C + (size_t)(m + 8) * N + n) = h1;
            } else {
                int h  = n / 40;
                int cc = n % 40;
                bool isq = cc < 20;
                int pos = isq ? cc : cc + 4;
                float s = isq ? 0.22360679774997896f : 1.0f;
                __half2 h0 = __floats2half2_rn(acc[i][j][0] * s, acc[i][j][1] * s);
                __half2 h1 = __floats2half2_rn(acc[i][j][2] * s, acc[i][j][3] * s);
                *(__half2*)(C + ((size_t)m * H_ + h) * TSH + pos)       = h0;
                *(__half2*)(C + ((size_t)(m + 8) * H_ + h) * TSH + pos) = h1;
            }
        }
    }
    #undef LOAD_STAGE
}

// ---------------------------------------------------------------------------
// Epilogue v11 = v8 + PREDICATED BIAS PREFETCH.
// Per kt, kk processed in 2 halves of 4. Before each half, 16 predicated
// scalar bias loads (single-statement if bodies -> @P LDG, front-batched,
// MLP ~16) fill bv[4][4]; the dot+store loop stays branchy (mask skip keeps
// bias/compute traffic minimal). occ bound 2 -> no spill pressure.
// Thread: h = tid&7, qg = (tid>>3)&7 (4 q rows), kg = tid>>6 (8 k rows).
// q: 4 rows x 10 half2 regs (loaded once). k smem: 8 planes x 776 halves.
// ---------------------------------------------------------------------------
#define PLANEH 776
#define EPKH (8*PLANEH)   // 12416 B

__global__ void __launch_bounds__(256, 2) attn_epilogue_kernel(
    const __half* __restrict__ ts, const int* __restrict__ mask,
    const float* __restrict__ bias, float* __restrict__ out)
{
    __shared__ __align__(16) __half ks[EPKH];

    const int b  = blockIdx.z;
    const int q0 = blockIdx.y * 32;
    const int h0 = blockIdx.x * 8;
    const int tid = threadIdx.x;
    const int h  = tid & 7;
    const int qg = (tid >> 3) & 7;   // 4 q rows each
    const int kg = tid >> 6;         // 8 k rows per iter (warp-uniform)
    const int frow = tid >> 3;       // fill: 0..31
    const int fh   = tid & 7;        // fill: 0..7

    // ---- load this thread's 4 q rows (head h0+h) as half2, once ----
    __half2 qh[4][10];
    {
        const size_t qrow_base = (size_t)(b * L_ + q0 + qg * 4) * H_;
        #pragma unroll
        for (int qq = 0; qq < 4; ++qq) {
            const __half* qsrc = ts + (qrow_base + (size_t)qq * H_ + h0 + h) * TSH;
            uint4 v0 = *(const uint4*)qsrc;
            uint4 v1 = *(const uint4*)(qsrc + 8);
            uint2 v2 = *(const uint2*)(qsrc + 16);
            qh[qq][0] = *(const __half2*)&v0.x;
            qh[qq][1] = *(const __half2*)&v0.y;
            qh[qq][2] = *(const __half2*)&v0.z;
            qh[qq][3] = *(const __half2*)&v0.w;
            qh[qq][4] = *(const __half2*)&v1.x;
            qh[qq][5] = *(const __half2*)&v1.y;
            qh[qq][6] = *(const __half2*)&v1.z;
            qh[qq][7] = *(const __half2*)&v1.w;
            qh[qq][8] = *(const __half2*)&v2.x;
            qh[qq][9] = *(const __half2*)&v2.y;
        }
    }

    for (int kt = 0; kt < 16; ++kt) {
        const int k0 = kt * 32;
        __syncthreads();   // previous iteration's consumers done with ks

        // fill k plane: one (row, head) segment per thread, raw 24-half copy
        {
            const __half* ksrc = ts + ((size_t)(b * L_ + k0 + frow) * H_ + h0 + fh) * TSH + 24;
            __half* kdst = ks + fh * PLANEH + frow * 24;
            *(uint4*)(kdst)      = *(const uint4*)(ksrc);
            *(uint4*)(kdst + 8)  = *(const uint4*)(ksrc + 8);
            *(uint4*)(kdst + 16) = *(const uint4*)(ksrc + 16);
        }
        __syncthreads();   // k plane visible

        int maskr[8];
        #pragma unroll
        for (int kk = 0; kk < 8; ++kk)
            maskr[kk] = mask[b * L_ + k0 + kg * 8 + kk];

        const __half* kplane = ks + h * PLANEH;
        const size_t obase = ((size_t)(b * L_ + q0 + qg * 4) * L_ + k0 + kg * 8) * H_
                           + h0 + h;

        #pragma unroll
        for (int half = 0; half < 2; ++half) {
            // ---- predicated bias prefetch (front-batched @P LDGs) ----
            float bv[4][4];
            #pragma unroll
            for (int k2 = 0; k2 < 4; ++k2) {
                const int kk = half * 4 + k2;
                const size_t okk = obase + (size_t)kk * H_;
                #pragma unroll
                for (int qq = 0; qq < 4; ++qq) {
                    float t = 0.0f;
                    if (maskr[kk]) t = __ldg(&bias[okk + (size_t)qq * (L_ * H_)]);
                    bv[k2][qq] = t;
                }
            }
            // ---- dot + store (branchy: skip compute for masked k) ----
            #pragma unroll
            for (int k2 = 0; k2 < 4; ++k2) {
                const int kk = half * 4 + k2;
                const size_t okk = obase + (size_t)kk * H_;
                if (maskr[kk]) {
                    __half2 kvh[10];
                    const __half* kp = kplane + (kg * 8 + kk) * 24;
                    uint4 a0 = *(const uint4*)kp;
                    uint4 a1 = *(const uint4*)(kp + 8);
                    uint2 a2 = *(const uint2*)(kp + 16);
                    kvh[0] = *(const __half2*)&a0.x;
                    kvh[1] = *(const __half2*)&a0.y;
                    kvh[2] = *(const __half2*)&a0.z;
                    kvh[3] = *(const __half2*)&a0.w;
                    kvh[4] = *(const __half2*)&a1.x;
                    kvh[5] = *(const __half2*)&a1.y;
                    kvh[6] = *(const __half2*)&a1.z;
                    kvh[7] = *(const __half2*)&a1.w;
                    kvh[8] = *(const __half2*)&a2.x;
                    kvh[9] = *(const __half2*)&a2.y;
                    #pragma unroll
                    for (int qq = 0; qq < 4; ++qq) {
                        __half2 acc0 = __hmul2(qh[qq][0], kvh[0]);
                        __half2 acc1 = __hmul2(qh[qq][1], kvh[1]);
                        #pragma unroll
                        for (int c = 1; c < 5; ++c) {
                            acc0 = __hfma2(qh[qq][2*c],   kvh[2*c],   acc0);
                            acc1 = __hfma2(qh[qq][2*c+1], kvh[2*c+1], acc1);
                        }
                        float2 f0 = __half22float2(acc0);
                        float2 f1 = __half22float2(acc1);
                        out[okk + (size_t)qq * (L_ * H_)] =
                            ((f0.x + f0.y) + (f1.x + f1.y)) + bv[k2][qq];
                    }
                } else {
                    #pragma unroll
                    for (int qq = 0; qq < 4; ++qq)
                        out[okk + (size_t)qq * (L_ * H_)] = 0.0f;
                }
            }
        }
    }
}

// ---------------------------------------------------------------------------
// launch: f2h_all(1), GEMM1(2), GEMM2(3), epilogue(4 -> profiled)
// ---------------------------------------------------------------------------
extern "C" void kernel_launch(void* const* d_in, const int* in_sizes, int n_in,
                              void* d_out, int out_size)
{
    const float* x      = (const float*)d_in[0];   // (B,L,T)
    const int*   mask   = (const int*)  d_in[1];   // (B,L) int32
    const float* bias   = (const float*)d_in[2];   // (B,L,L,H)
    const float* W_up   = (const float*)d_in[3];   // (E,T)
    const float* W_proj = (const float*)d_in[4];   // (2E,E)
    float* out = (float*)d_out;

    __half *xh, *wuh, *wph, *xeh, *ts;
    cudaGetSymbolAddress((void**)&xh,  g_xh);
    cudaGetSymbolAddress((void**)&wuh, g_wuh);
    cudaGetSymbolAddress((void**)&wph, g_wph);
    cudaGetSymbolAddress((void**)&xeh, g_xeh);
    cudaGetSymbolAddress((void**)&ts,  g_ts);

    cudaFuncSetAttribute((const void*)gemm_f16<0>,
                         cudaFuncAttributeMaxDynamicSharedMemorySize, GSMEM_BYTES);
    cudaFuncSetAttribute((const void*)gemm_f16<2>,
                         cudaFuncAttributeMaxDynamicSharedMemorySize, GSMEM_BYTES);

    // merged f32 -> f16 conversion (one launch)
    f2h_all_kernel<<<2368, 256>>>((const float4*)x, (const float4*)W_up,
                                  (const float4*)W_proj,
                                  (uint2*)xh, (uint2*)wuh, (uint2*)wph);

    // GEMM1: xe_h(1024,2560) = x_h @ W_up_h^T   (320 CTAs)
    {
        dim3 grid(B_*L_ / BMT, E_ / BN);
        gemm_f16<0><<<grid, 256, GSMEM_BYTES>>>(xh, wuh, xeh, B_*L_, E_, T_);
    }
    // GEMM2: ts split layout = xe_h @ W_proj_h^T  (640 CTAs)
    {
        dim3 grid(B_*L_ / BMT, F_ / BN);
        gemm_f16<2><<<grid, 256, GSMEM_BYTES>>>(xeh, wph, ts, B_*L_, F_, E_);
    }
    // fused q.k^T + bias + mask epilogue
    {
        dim3 grid(H_ / 8, L_ / 32, B_);
        attn_epilogue_kernel<<<grid, 256>>>(ts, mask, bias, out);
    }
}